// round 15
// baseline (speedup 1.0000x reference)
#include <cuda_runtime.h>

// Weighted BCE loss, mean-reduced, single fused kernel.
// loss_i = (t_i==1) ? -log(o_i + eps) : -8 * log(1 - o_i + eps);  out = mean(loss)
// Blocked (contiguous per-block segment) partitioning for DRAM row locality,
// streaming loads, last-block finalize.

#define NEG_WEIGHT 8.0f
#define BCE_EPS    1e-7f

// Exactly one wave: 148 SMs x 8 resident blocks (256 thr, <=32 regs)
#define NBLOCKS  1184
#define NTHREADS 256

__device__ double       g_acc;    // zero-init; reset by last block each launch
__device__ unsigned int g_count;  // zero-init; reset by last block each launch

__device__ __forceinline__ float bce_elem(float o, int t) {
    // one log per element: x = t ? o : 1-o ; w = t ? 1 : 8
    float x = (t == 1) ? o : (1.0f - o);
    float w = (t == 1) ? 1.0f : NEG_WEIGHT;
    return w * (-__logf(x + BCE_EPS));
}

__device__ __forceinline__ float bce_quad(float4 o, int4 t) {
    // two independent chains to shorten FADD dependency
    float a = bce_elem(o.x, t.x) + bce_elem(o.z, t.z);
    float b = bce_elem(o.y, t.y) + bce_elem(o.w, t.w);
    return a + b;
}

__global__ void __launch_bounds__(NTHREADS)
bce_fused_kernel(const float4* __restrict__ out4,
                 const int4*   __restrict__ tgt4,
                 const float*  __restrict__ out_s,
                 const int*    __restrict__ tgt_s,
                 float* __restrict__ result,
                 int n4, int n, int seg)
{
    const int tid   = threadIdx.x;
    const int start = blockIdx.x * seg;
    int end = start + seg;
    if (end > n4) end = n4;

    float acc0 = 0.0f, acc1 = 0.0f;

    // Walk the block's contiguous segment: 2 consecutive 4KB slabs per stream
    // per iteration (8KB contiguous bursts -> DRAM row-buffer friendly).
    int base = start;
    for (; base + 2 * NTHREADS <= end; base += 2 * NTHREADS) {
        int i0 = base + tid;
        int i1 = base + NTHREADS + tid;
        float4 o0 = __ldcs(&out4[i0]);
        float4 o1 = __ldcs(&out4[i1]);
        int4   t0 = __ldcs(&tgt4[i0]);
        int4   t1 = __ldcs(&tgt4[i1]);
        acc0 += bce_quad(o0, t0);
        acc1 += bce_quad(o1, t1);
    }
    for (int i = base + tid; i < end; i += NTHREADS) {
        float4 o0 = __ldcs(&out4[i]);
        int4   t0 = __ldcs(&tgt4[i]);
        acc0 += bce_quad(o0, t0);
    }

    float acc = acc0 + acc1;

    // scalar tail (n not divisible by 4)
    if (blockIdx.x == 0 && tid == 0) {
        for (int k = n4 * 4; k < n; k++)
            acc += bce_elem(out_s[k], tgt_s[k]);
    }

    // intra-block reduction: warp shuffle, then smem across warps
    #pragma unroll
    for (int off = 16; off > 0; off >>= 1)
        acc += __shfl_down_sync(0xffffffffu, acc, off);

    __shared__ float s_warp[NTHREADS / 32];
    if ((tid & 31) == 0)
        s_warp[tid >> 5] = acc;
    __syncthreads();

    if (tid == 0) {
        float bsum = 0.0f;
        #pragma unroll
        for (int w = 0; w < NTHREADS / 32; w++)
            bsum += s_warp[w];

        // cross-block accumulation in double, last block finalizes
        atomicAdd(&g_acc, (double)bsum);
        __threadfence();
        unsigned int old = atomicAdd(&g_count, 1u);
        if (old == gridDim.x - 1) {
            double total = g_acc;
            result[0] = (float)(total / (double)n);
            // reset for next graph replay
            g_acc   = 0.0;
            g_count = 0u;
            __threadfence();
        }
    }
}

extern "C" void kernel_launch(void* const* d_in, const int* in_sizes, int n_in,
                              void* d_out, int out_size)
{
    const float* outputs = (const float*)d_in[0];
    const int*   targets = (const int*)d_in[1];
    float* out = (float*)d_out;

    int n  = in_sizes[0];
    int n4 = n >> 2;
    int seg = (n4 + NBLOCKS - 1) / NBLOCKS;

    bce_fused_kernel<<<NBLOCKS, NTHREADS>>>(
        (const float4*)outputs, (const int4*)targets,
        outputs, targets, out, n4, n, seg);
}

// round 16
// speedup vs baseline: 1.0936x; 1.0936x over previous
#include <cuda_runtime.h>

// Weighted BCE loss, mean-reduced, single fused kernel.
// loss_i = (t_i==1) ? -log(o_i + eps) : -8 * log(1 - o_i + eps);  out = mean(loss)
// Grid-stride (best-measured layout), streaming loads with L2::256B prefetch,
// one-wave launch, last-block finalize.

#define NEG_WEIGHT 8.0f
#define BCE_EPS    1e-7f

// Exactly one wave: 148 SMs x 8 resident blocks (256 thr, <=32 regs)
#define NBLOCKS  1184
#define NTHREADS 256

__device__ double       g_acc;    // zero-init; reset by last block each launch
__device__ unsigned int g_count;  // zero-init; reset by last block each launch

__device__ __forceinline__ float4 ld_stream_f4(const float4* p) {
    float4 v;
    asm volatile("ld.global.cs.L2::256B.v4.f32 {%0,%1,%2,%3}, [%4];"
                 : "=f"(v.x), "=f"(v.y), "=f"(v.z), "=f"(v.w) : "l"(p));
    return v;
}

__device__ __forceinline__ int4 ld_stream_i4(const int4* p) {
    int4 v;
    asm volatile("ld.global.cs.L2::256B.v4.b32 {%0,%1,%2,%3}, [%4];"
                 : "=r"(v.x), "=r"(v.y), "=r"(v.z), "=r"(v.w) : "l"(p));
    return v;
}

__device__ __forceinline__ float bce_elem(float o, int t) {
    // one log per element: x = t ? o : 1-o ; w = t ? 1 : 8
    float x = (t == 1) ? o : (1.0f - o);
    float w = (t == 1) ? 1.0f : NEG_WEIGHT;
    return w * (-__logf(x + BCE_EPS));
}

__device__ __forceinline__ float bce_quad(float4 o, int4 t) {
    // two independent chains to shorten FADD dependency
    float a = bce_elem(o.x, t.x) + bce_elem(o.z, t.z);
    float b = bce_elem(o.y, t.y) + bce_elem(o.w, t.w);
    return a + b;
}

__global__ void __launch_bounds__(NTHREADS)
bce_fused_kernel(const float4* __restrict__ out4,
                 const int4*   __restrict__ tgt4,
                 const float*  __restrict__ out_s,
                 const int*    __restrict__ tgt_s,
                 float* __restrict__ result,
                 int n4, int n)
{
    const int idx    = blockIdx.x * blockDim.x + threadIdx.x;
    const int stride = gridDim.x * blockDim.x;

    float acc0 = 0.0f, acc1 = 0.0f;

    // 2x unrolled grid-stride: 4 front-batched streaming LDG.128 per iteration
    int i = idx;
    for (; i + stride < n4; i += 2 * stride) {
        float4 o0 = ld_stream_f4(&out4[i]);
        float4 o1 = ld_stream_f4(&out4[i + stride]);
        int4   t0 = ld_stream_i4(&tgt4[i]);
        int4   t1 = ld_stream_i4(&tgt4[i + stride]);
        acc0 += bce_quad(o0, t0);
        acc1 += bce_quad(o1, t1);
    }
    if (i < n4) {
        float4 o0 = ld_stream_f4(&out4[i]);
        int4   t0 = ld_stream_i4(&tgt4[i]);
        acc0 += bce_quad(o0, t0);
    }

    float acc = acc0 + acc1;

    // scalar tail (n not divisible by 4)
    if (idx == 0) {
        for (int k = n4 * 4; k < n; k++)
            acc += bce_elem(out_s[k], tgt_s[k]);
    }

    // intra-block reduction: warp shuffle, then smem across warps
    #pragma unroll
    for (int off = 16; off > 0; off >>= 1)
        acc += __shfl_down_sync(0xffffffffu, acc, off);

    __shared__ float s_warp[NTHREADS / 32];
    if ((threadIdx.x & 31) == 0)
        s_warp[threadIdx.x >> 5] = acc;
    __syncthreads();

    if (threadIdx.x == 0) {
        float bsum = 0.0f;
        #pragma unroll
        for (int w = 0; w < NTHREADS / 32; w++)
            bsum += s_warp[w];

        // cross-block accumulation in double, last block finalizes
        atomicAdd(&g_acc, (double)bsum);
        __threadfence();
        unsigned int old = atomicAdd(&g_count, 1u);
        if (old == gridDim.x - 1) {
            double total = g_acc;
            result[0] = (float)(total / (double)n);
            // reset for next graph replay
            g_acc   = 0.0;
            g_count = 0u;
            __threadfence();
        }
    }
}

extern "C" void kernel_launch(void* const* d_in, const int* in_sizes, int n_in,
                              void* d_out, int out_size)
{
    const float* outputs = (const float*)d_in[0];
    const int*   targets = (const int*)d_in[1];
    float* out = (float*)d_out;

    int n  = in_sizes[0];
    int n4 = n >> 2;

    bce_fused_kernel<<<NBLOCKS, NTHREADS>>>(
        (const float4*)outputs, (const int4*)targets,
        outputs, targets, out, n4, n);
}

// round 17
// speedup vs baseline: 1.1330x; 1.0360x over previous
#include <cuda_runtime.h>

// Weighted BCE loss, mean-reduced, single fused kernel.
// loss_i = (t_i==1) ? -log(o_i + eps) : -8 * log(1 - o_i + eps);  out = mean(loss)
// Best-measured config (R9): grid-stride interleave, __ldcs streaming loads,
// one-wave launch (1184x256, 8 blocks/SM), fused last-block finalize.
// Converged at ~6.25 TB/s dual-stream read — the measured fabric ceiling.

#define NEG_WEIGHT 8.0f
#define BCE_EPS    1e-7f

// Exactly one wave: 148 SMs x 8 resident blocks (256 thr, <=32 regs)
#define NBLOCKS  1184
#define NTHREADS 256

__device__ double       g_acc;    // zero-init; reset by last block each launch
__device__ unsigned int g_count;  // zero-init; reset by last block each launch

__device__ __forceinline__ float bce_elem(float o, int t) {
    // one log per element: x = t ? o : 1-o ; w = t ? 1 : 8
    float x = (t == 1) ? o : (1.0f - o);
    float w = (t == 1) ? 1.0f : NEG_WEIGHT;
    return w * (-__logf(x + BCE_EPS));
}

__device__ __forceinline__ float bce_quad(float4 o, int4 t) {
    // two independent chains to shorten FADD dependency
    float a = bce_elem(o.x, t.x) + bce_elem(o.z, t.z);
    float b = bce_elem(o.y, t.y) + bce_elem(o.w, t.w);
    return a + b;
}

__global__ void __launch_bounds__(NTHREADS)
bce_fused_kernel(const float4* __restrict__ out4,
                 const int4*   __restrict__ tgt4,
                 const float*  __restrict__ out_s,
                 const int*    __restrict__ tgt_s,
                 float* __restrict__ result,
                 int n4, int n)
{
    const int idx    = blockIdx.x * blockDim.x + threadIdx.x;
    const int stride = gridDim.x * blockDim.x;

    float acc0 = 0.0f, acc1 = 0.0f;

    // 2x unrolled grid-stride: 4 front-batched streaming LDG.128 per iteration
    int i = idx;
    for (; i + stride < n4; i += 2 * stride) {
        float4 o0 = __ldcs(&out4[i]);
        int4   t0 = __ldcs(&tgt4[i]);
        float4 o1 = __ldcs(&out4[i + stride]);
        int4   t1 = __ldcs(&tgt4[i + stride]);
        acc0 += bce_quad(o0, t0);
        acc1 += bce_quad(o1, t1);
    }
    if (i < n4) {
        float4 o0 = __ldcs(&out4[i]);
        int4   t0 = __ldcs(&tgt4[i]);
        acc0 += bce_quad(o0, t0);
    }

    float acc = acc0 + acc1;

    // scalar tail (n not divisible by 4)
    if (idx == 0) {
        for (int k = n4 * 4; k < n; k++)
            acc += bce_elem(out_s[k], tgt_s[k]);
    }

    // intra-block reduction: warp shuffle, then smem across warps
    #pragma unroll
    for (int off = 16; off > 0; off >>= 1)
        acc += __shfl_down_sync(0xffffffffu, acc, off);

    __shared__ float s_warp[NTHREADS / 32];
    if ((threadIdx.x & 31) == 0)
        s_warp[threadIdx.x >> 5] = acc;
    __syncthreads();

    if (threadIdx.x == 0) {
        float bsum = 0.0f;
        #pragma unroll
        for (int w = 0; w < NTHREADS / 32; w++)
            bsum += s_warp[w];

        // cross-block accumulation in double, last block finalizes
        atomicAdd(&g_acc, (double)bsum);
        __threadfence();
        unsigned int old = atomicAdd(&g_count, 1u);
        if (old == gridDim.x - 1) {
            double total = g_acc;
            result[0] = (float)(total / (double)n);
            // reset for next graph replay
            g_acc   = 0.0;
            g_count = 0u;
            __threadfence();
        }
    }
}

extern "C" void kernel_launch(void* const* d_in, const int* in_sizes, int n_in,
                              void* d_out, int out_size)
{
    const float* outputs = (const float*)d_in[0];
    const int*   targets = (const int*)d_in[1];
    float* out = (float*)d_out;

    int n  = in_sizes[0];
    int n4 = n >> 2;

    bce_fused_kernel<<<NBLOCKS, NTHREADS>>>(
        (const float4*)outputs, (const int4*)targets,
        outputs, targets, out, n4, n);
}